// round 3
// baseline (speedup 1.0000x reference)
#include <cuda_runtime.h>
#include <cstdint>

#define N_ 50000
#define E_ 800000

// ---------------- scratch (device globals; no allocation) ----------------
__device__ __align__(16) float d_x   [N_*36];
__device__ __align__(16) float d_ea  [E_*16];
__device__ __align__(16) float d_msg [E_*36];
__device__ __align__(16) float d_agg [N_*128];
__device__ __align__(16) float d_h   [N_*128];
__device__ __align__(16) float d_h2  [N_*128];
__device__ __align__(16) float d_xl  [N_*128];
__device__ __align__(16) float d_xr  [N_*128];
__device__ __align__(16) float d_den  [N_*2];
__device__ __align__(16) float d_out2[N_*128];
__device__ __align__(16) float d_easum[16];

// ---------------- helpers ----------------
__device__ __forceinline__ void redAdd4(float* addr, float a, float b, float c, float d) {
    asm volatile("red.global.add.v4.f32 [%0], {%1, %2, %3, %4};"
                 :: "l"(addr), "f"(a), "f"(b), "f"(c), "f"(d) : "memory");
}

__device__ __forceinline__ float lrelu(float x) {
    return x > 0.0f ? x : 0.2f * x;
}

#define FMA4(acc, s, wv) { acc.x += (s)*(wv).x; acc.y += (s)*(wv).y; acc.z += (s)*(wv).z; acc.w += (s)*(wv).w; }

// ---------------- feature assembly ----------------
__global__ void k_node_feat(const int* __restrict__ xcat, const float* __restrict__ xcont,
                            const float* __restrict__ emb) {
    int i = blockIdx.x * blockDim.x + threadIdx.x;
    if (i >= N_ * 36) return;
    int n = i / 36, j = i - n * 36;
    float v;
    if (j < 20) v = emb[xcat[n] * 20 + j];
    else        v = xcont[n * 16 + (j - 20)];
    d_x[i] = v;
}

__global__ void k_edge_feat(const int* __restrict__ ecat, const float* __restrict__ econt,
                            const float* __restrict__ emb) {
    int i = blockIdx.x * blockDim.x + threadIdx.x;
    if (i >= E_ * 16) return;
    int e = i >> 4, j = i & 15;
    float v;
    if (j < 4) v = emb[ecat[e] * 4 + j];
    else       v = econt[e * 12 + (j - 4)];
    d_ea[i] = v;
}

// sum of ea over edges (for self-loop edge attr mean)
__global__ void k_easum() {
    int tid = blockIdx.x * blockDim.x + threadIdx.x;
    int stride = gridDim.x * blockDim.x;
    float a[16];
#pragma unroll
    for (int j = 0; j < 16; j++) a[j] = 0.0f;
    for (int e = tid; e < E_; e += stride) {
        const float4* p = ((const float4*)d_ea) + (size_t)e * 4;
        float4 v0 = p[0], v1 = p[1], v2 = p[2], v3 = p[3];
        a[0]+=v0.x; a[1]+=v0.y; a[2]+=v0.z; a[3]+=v0.w;
        a[4]+=v1.x; a[5]+=v1.y; a[6]+=v1.z; a[7]+=v1.w;
        a[8]+=v2.x; a[9]+=v2.y; a[10]+=v2.z; a[11]+=v2.w;
        a[12]+=v3.x; a[13]+=v3.y; a[14]+=v3.z; a[15]+=v3.w;
    }
#pragma unroll
    for (int off = 16; off; off >>= 1)
#pragma unroll
        for (int j = 0; j < 16; j++) a[j] += __shfl_down_sync(0xffffffffu, a[j], off);
    if ((threadIdx.x & 31) == 0)
#pragma unroll
        for (int j = 0; j < 16; j++) atomicAdd(&d_easum[j], a[j]);
}

// ---------------- GINE1 phase A: msg_lin = ea @ W1 + b1 (thread per edge) ----------------
__global__ __launch_bounds__(256) void k_lin1(const float* __restrict__ W, const float* __restrict__ b) {
    __shared__ float Ws[16 * 36];
    __shared__ float bs[36];
    int t = threadIdx.x;
    for (int i = t; i < 16 * 36; i += 256) Ws[i] = W[i];
    if (t < 36) bs[t] = b[t];
    __syncthreads();
    int e = blockIdx.x * 256 + t;
    if (e >= E_) return;
    const float4* eap = ((const float4*)d_ea) + (size_t)e * 4;
    float4 e0 = eap[0], e1 = eap[1], e2 = eap[2], e3 = eap[3];
    float ev[16] = {e0.x,e0.y,e0.z,e0.w, e1.x,e1.y,e1.z,e1.w,
                    e2.x,e2.y,e2.z,e2.w, e3.x,e3.y,e3.z,e3.w};
    float4* mout = (float4*)(d_msg + (size_t)e * 36);
#pragma unroll
    for (int g = 0; g < 9; g++) {
        float4 acc = *(const float4*)(bs + g * 4);
#pragma unroll
        for (int k = 0; k < 16; k++) {
            float4 wv = *(const float4*)(Ws + k * 36 + g * 4);
            FMA4(acc, ev[k], wv);
        }
        mout[g] = acc;
    }
}

// ---------------- GINE1 phase B: agg[dst] += relu(x[src] + msg) ----------------
__global__ __launch_bounds__(256) void k_scatter1(const int* __restrict__ src, const int* __restrict__ dst) {
    int i = blockIdx.x * 256 + threadIdx.x;   // i in [0, E*9)
    if (i >= E_ * 9) return;
    int e = i / 9, g = i - e * 9;
    int s = src[e], d = dst[e];
    float4 m = ((const float4*)d_msg)[i];
    float4 xv = *(const float4*)(d_x + (size_t)s * 36 + g * 4);
    redAdd4(&d_agg[(size_t)d * 36 + g * 4],
            fmaxf(m.x + xv.x, 0.0f), fmaxf(m.y + xv.y, 0.0f),
            fmaxf(m.z + xv.z, 0.0f), fmaxf(m.w + xv.w, 0.0f));
}

// ---------------- GINE2 fused: weights in registers, persistent warps ----------------
__global__ __launch_bounds__(256) void k_gine2_fused(const int* __restrict__ src, const int* __restrict__ dst,
                                                     const float* __restrict__ W, const float* __restrict__ b) {
    int lane = threadIdx.x & 31;
    int gw = (blockIdx.x * 256 + threadIdx.x) >> 5;
    int nw = (gridDim.x * 256) >> 5;
    float4 Wr[16];
#pragma unroll
    for (int k = 0; k < 16; k++) Wr[k] = ((const float4*)W)[k * 32 + lane];
    float4 bv = ((const float4*)b)[lane];
    for (int e = gw; e < E_; e += nw) {
        int s = src[e], d = dst[e];
        const float4* eap = ((const float4*)d_ea) + (size_t)e * 4;
        float4 e0 = eap[0], e1 = eap[1], e2 = eap[2], e3 = eap[3];
        float4 acc = bv;
        FMA4(acc, e0.x, Wr[0]);  FMA4(acc, e0.y, Wr[1]);  FMA4(acc, e0.z, Wr[2]);  FMA4(acc, e0.w, Wr[3]);
        FMA4(acc, e1.x, Wr[4]);  FMA4(acc, e1.y, Wr[5]);  FMA4(acc, e1.z, Wr[6]);  FMA4(acc, e1.w, Wr[7]);
        FMA4(acc, e2.x, Wr[8]);  FMA4(acc, e2.y, Wr[9]);  FMA4(acc, e2.z, Wr[10]); FMA4(acc, e2.w, Wr[11]);
        FMA4(acc, e3.x, Wr[12]); FMA4(acc, e3.y, Wr[13]); FMA4(acc, e3.z, Wr[14]); FMA4(acc, e3.w, Wr[15]);
        float4 hv = ((const float4*)d_h)[(size_t)s * 32 + lane];
        redAdd4(&d_agg[(size_t)d * 128 + lane * 4],
                fmaxf(hv.x + acc.x, 0.0f), fmaxf(hv.y + acc.y, 0.0f),
                fmaxf(hv.z + acc.z, 0.0f), fmaxf(hv.w + acc.w, 0.0f));
    }
}

// ---------------- node MLP, register-tiled: 4 rows per thread ----------------
template <int K, bool HASAGG, bool HASBN>
__global__ __launch_bounds__(256) void k_mlp(
    const float* __restrict__ xin, const float* __restrict__ agg,
    const float* __restrict__ epsp,
    const float* __restrict__ W, const float* __restrict__ bias,
    const float* __restrict__ bng, const float* __restrict__ bnb,
    const float* __restrict__ bnm, const float* __restrict__ bnv,
    float* __restrict__ out)
{
    extern __shared__ float sm[];
    float* Ws  = sm;             // K*128
    float* tin = sm + K * 128;   // 32*K
    int tid = threadIdx.x;
    int lane = tid & 31, w = tid >> 5;
    for (int i = tid; i < K * 32; i += 256) ((float4*)Ws)[i] = ((const float4*)W)[i];
    int c = lane * 4;
    float4 bv = *(const float4*)(bias + c);
    float4 scale = make_float4(1,1,1,1), shift = make_float4(0,0,0,0);
    if (HASBN) {
        float s0 = bng[c+0] * rsqrtf(bnv[c+0] + 1e-5f);
        float s1 = bng[c+1] * rsqrtf(bnv[c+1] + 1e-5f);
        float s2 = bng[c+2] * rsqrtf(bnv[c+2] + 1e-5f);
        float s3 = bng[c+3] * rsqrtf(bnv[c+3] + 1e-5f);
        scale = make_float4(s0, s1, s2, s3);
        shift = make_float4(bnb[c+0] - bnm[c+0]*s0, bnb[c+1] - bnm[c+1]*s1,
                            bnb[c+2] - bnm[c+2]*s2, bnb[c+3] - bnm[c+3]*s3);
    }
    float sx = HASAGG ? (1.0f + *epsp) : 1.0f;
    __syncthreads();

    for (int base = blockIdx.x * 32; base < N_; base += gridDim.x * 32) {
        for (int i = tid; i < 32 * K; i += 256) {
            int r = i / K, k = i - r * K;
            int n = base + r;
            if (n < N_) {
                float tv = xin[(size_t)n * K + k] * sx;
                if (HASAGG) tv += agg[(size_t)n * K + k];
                tin[i] = tv;
            }
        }
        __syncthreads();
        const float* t0 = tin + (w * 4) * K;
        float4 a0 = bv, a1 = bv, a2 = bv, a3 = bv;
#pragma unroll 8
        for (int k = 0; k < K; k++) {
            float4 wv = *(const float4*)(Ws + k * 128 + c);
            float k0 = t0[k], k1 = t0[K + k], k2 = t0[2 * K + k], k3 = t0[3 * K + k];
            FMA4(a0, k0, wv); FMA4(a1, k1, wv); FMA4(a2, k2, wv); FMA4(a3, k3, wv);
        }
        if (HASBN) {
            a0.x = fmaxf(a0.x,0.f)*scale.x+shift.x; a0.y = fmaxf(a0.y,0.f)*scale.y+shift.y;
            a0.z = fmaxf(a0.z,0.f)*scale.z+shift.z; a0.w = fmaxf(a0.w,0.f)*scale.w+shift.w;
            a1.x = fmaxf(a1.x,0.f)*scale.x+shift.x; a1.y = fmaxf(a1.y,0.f)*scale.y+shift.y;
            a1.z = fmaxf(a1.z,0.f)*scale.z+shift.z; a1.w = fmaxf(a1.w,0.f)*scale.w+shift.w;
            a2.x = fmaxf(a2.x,0.f)*scale.x+shift.x; a2.y = fmaxf(a2.y,0.f)*scale.y+shift.y;
            a2.z = fmaxf(a2.z,0.f)*scale.z+shift.z; a2.w = fmaxf(a2.w,0.f)*scale.w+shift.w;
            a3.x = fmaxf(a3.x,0.f)*scale.x+shift.x; a3.y = fmaxf(a3.y,0.f)*scale.y+shift.y;
            a3.z = fmaxf(a3.z,0.f)*scale.z+shift.z; a3.w = fmaxf(a3.w,0.f)*scale.w+shift.w;
        }
        int n0 = base + w * 4;
        if (n0 + 0 < N_) *(float4*)(out + (size_t)(n0+0) * 128 + c) = a0;
        if (n0 + 1 < N_) *(float4*)(out + (size_t)(n0+1) * 128 + c) = a1;
        if (n0 + 2 < N_) *(float4*)(out + (size_t)(n0+2) * 128 + c) = a2;
        if (n0 + 3 < N_) *(float4*)(out + (size_t)(n0+3) * 128 + c) = a3;
        __syncthreads();
    }
}

// ---------------- GATv2 node pass: self-loop initializes out2/den ----------------
__global__ void k_gat_node(const float* __restrict__ Wg, const float* __restrict__ attv) {
    __shared__ float eeLs[128];
    __shared__ float4 atts[32];
    int t = threadIdx.x;
    if (t < 128) {
        float s = 0.0f;
#pragma unroll
        for (int k = 0; k < 16; k++) s += d_easum[k] * Wg[k * 128 + t];
        eeLs[t] = s * (1.0f / (float)E_);
    }
    if (t < 32) atts[t] = ((const float4*)attv)[t];
    __syncthreads();
    int n = (blockIdx.x * blockDim.x + t) >> 5;
    int lane = t & 31;
    if (n >= N_) return;
    float4 ev  = ((const float4*)eeLs)[lane];
    float4 xlv = ((const float4*)d_xl)[(size_t)n * 32 + lane];
    float4 xrv = ((const float4*)d_xr)[(size_t)n * 32 + lane];
    float4 av = atts[lane];
    float p = lrelu(xlv.x + xrv.x + ev.x) * av.x
            + lrelu(xlv.y + xrv.y + ev.y) * av.y
            + lrelu(xlv.z + xrv.z + ev.z) * av.z
            + lrelu(xlv.w + xrv.w + ev.w) * av.w;
    p += __shfl_xor_sync(0xffffffffu, p, 1);
    p += __shfl_xor_sync(0xffffffffu, p, 2);
    p += __shfl_xor_sync(0xffffffffu, p, 4);
    p += __shfl_xor_sync(0xffffffffu, p, 8);
    float ex = __expf(p);
    ((float4*)d_out2)[(size_t)n * 32 + lane] =
        make_float4(ex * xlv.x, ex * xlv.y, ex * xlv.z, ex * xlv.w);
    if (lane == 0)  d_den[(size_t)n * 2 + 0] = ex;
    if (lane == 16) d_den[(size_t)n * 2 + 1] = ex;
}

// ---------------- GATv2 edge pass: weights in registers, single pass ----------------
__global__ __launch_bounds__(256) void k_gat_edge(const int* __restrict__ src, const int* __restrict__ dst,
                                                  const float* __restrict__ Wg, const float* __restrict__ attv) {
    int lane = threadIdx.x & 31;
    int gw = (blockIdx.x * 256 + threadIdx.x) >> 5;
    int nw = (gridDim.x * 256) >> 5;
    float4 Wr[16];
#pragma unroll
    for (int k = 0; k < 16; k++) Wr[k] = ((const float4*)Wg)[k * 32 + lane];
    float4 av = ((const float4*)attv)[lane];
    for (int e = gw; e < E_; e += nw) {
        int s = src[e], d = dst[e];
        const float4* eap = ((const float4*)d_ea) + (size_t)e * 4;
        float4 e0 = eap[0], e1 = eap[1], e2 = eap[2], e3 = eap[3];
        float4 acc = make_float4(0, 0, 0, 0);
        FMA4(acc, e0.x, Wr[0]);  FMA4(acc, e0.y, Wr[1]);  FMA4(acc, e0.z, Wr[2]);  FMA4(acc, e0.w, Wr[3]);
        FMA4(acc, e1.x, Wr[4]);  FMA4(acc, e1.y, Wr[5]);  FMA4(acc, e1.z, Wr[6]);  FMA4(acc, e1.w, Wr[7]);
        FMA4(acc, e2.x, Wr[8]);  FMA4(acc, e2.y, Wr[9]);  FMA4(acc, e2.z, Wr[10]); FMA4(acc, e2.w, Wr[11]);
        FMA4(acc, e3.x, Wr[12]); FMA4(acc, e3.y, Wr[13]); FMA4(acc, e3.z, Wr[14]); FMA4(acc, e3.w, Wr[15]);
        float4 xlv = ((const float4*)d_xl)[(size_t)s * 32 + lane];
        float4 xrv = ((const float4*)d_xr)[(size_t)d * 32 + lane];
        float p = lrelu(xlv.x + xrv.x + acc.x) * av.x
                + lrelu(xlv.y + xrv.y + acc.y) * av.y
                + lrelu(xlv.z + xrv.z + acc.z) * av.z
                + lrelu(xlv.w + xrv.w + acc.w) * av.w;
        p += __shfl_xor_sync(0xffffffffu, p, 1);
        p += __shfl_xor_sync(0xffffffffu, p, 2);
        p += __shfl_xor_sync(0xffffffffu, p, 4);
        p += __shfl_xor_sync(0xffffffffu, p, 8);
        float ex = __expf(p);
        redAdd4(&d_out2[(size_t)d * 128 + lane * 4],
                ex * xlv.x, ex * xlv.y, ex * xlv.z, ex * xlv.w);
        if (lane == 0)  atomicAdd(&d_den[(size_t)d * 2 + 0], ex);
        if (lane == 16) atomicAdd(&d_den[(size_t)d * 2 + 1], ex);
    }
}

__global__ void k_final(float* __restrict__ out, const float* __restrict__ bias) {
    int i = blockIdx.x * blockDim.x + threadIdx.x;
    if (i >= N_ * 64) return;
    int n = i >> 6, cc = i & 63;
    float2 dn = ((const float2*)d_den)[n];
    const float* o2 = d_out2 + (size_t)n * 128;
    out[i] = 0.5f * (o2[cc] / dn.x + o2[64 + cc] / dn.y) + bias[cc];
}

// ---------------- launch ----------------
extern "C" void kernel_launch(void* const* d_in, const int* in_sizes, int n_in,
                              void* d_out, int out_size) {
    const int*   x_cat    = (const int*)  d_in[0];
    const float* x_cont   = (const float*)d_in[1];
    const int*   e_cat    = (const int*)  d_in[2];
    const float* e_cont   = (const float*)d_in[3];
    const int*   eidx     = (const int*)  d_in[4];
    const int*   src = eidx;
    const int*   dst = eidx + E_;
    const float* node_emb = (const float*)d_in[5];
    const float* edge_emb = (const float*)d_in[6];
    const float* eps1     = (const float*)d_in[7];
    const float* W1e      = (const float*)d_in[8];
    const float* b1e      = (const float*)d_in[9];
    const float* nnW1     = (const float*)d_in[10];
    const float* nnb1     = (const float*)d_in[11];
    const float* g1 = (const float*)d_in[12], *bb1 = (const float*)d_in[13];
    const float* m1 = (const float*)d_in[14], *v1  = (const float*)d_in[15];
    const float* eps2     = (const float*)d_in[16];
    const float* W2e      = (const float*)d_in[17];
    const float* b2e      = (const float*)d_in[18];
    const float* nnW2     = (const float*)d_in[19];
    const float* nnb2     = (const float*)d_in[20];
    const float* g2 = (const float*)d_in[21], *bb2 = (const float*)d_in[22];
    const float* m2 = (const float*)d_in[23], *v2  = (const float*)d_in[24];
    const float* Wl  = (const float*)d_in[25], *bl = (const float*)d_in[26];
    const float* Wr  = (const float*)d_in[27], *br = (const float*)d_in[28];
    const float* Weg = (const float*)d_in[29];
    const float* att = (const float*)d_in[30];
    const float* gbias = (const float*)d_in[31];
    float* out = (float*)d_out;

    void *p_x, *p_agg, *p_h, *p_h2, *p_xl, *p_xr, *p_easum;
    cudaGetSymbolAddress(&p_x,    d_x);
    cudaGetSymbolAddress(&p_agg,  d_agg);
    cudaGetSymbolAddress(&p_h,    d_h);
    cudaGetSymbolAddress(&p_h2,   d_h2);
    cudaGetSymbolAddress(&p_xl,   d_xl);
    cudaGetSymbolAddress(&p_xr,   d_xr);
    cudaGetSymbolAddress(&p_easum,d_easum);

    const int smem36  = (36 * 128 + 32 * 36) * 4;
    const int smem128 = (128 * 128 + 32 * 128) * 4;
    cudaFuncSetAttribute(k_mlp<128, true,  true >, cudaFuncAttributeMaxDynamicSharedMemorySize, smem128);
    cudaFuncSetAttribute(k_mlp<128, false, false>, cudaFuncAttributeMaxDynamicSharedMemorySize, smem128);

    // init
    cudaMemsetAsync(p_easum, 0, 16 * 4);
    cudaMemsetAsync(p_agg,   0, (size_t)N_ * 36 * 4);

    // features
    k_node_feat<<<(N_ * 36 + 255) / 256, 256>>>(x_cat, x_cont, node_emb);
    k_edge_feat<<<(E_ * 16 + 255) / 256, 256>>>(e_cat, e_cont, edge_emb);
    k_easum<<<512, 256>>>();

    // GINE layer 1: pre-GEMM + light scatter
    k_lin1<<<(E_ + 255) / 256, 256>>>(W1e, b1e);
    k_scatter1<<<(E_ * 9 + 255) / 256, 256>>>(src, dst);
    k_mlp<36, true, true><<<296, 256, smem36>>>(
        (const float*)p_x, (const float*)p_agg, eps1, nnW1, nnb1, g1, bb1, m1, v1, (float*)p_h);

    // GINE layer 2: fused register-weight kernel
    cudaMemsetAsync(p_agg, 0, (size_t)N_ * 128 * 4);
    k_gine2_fused<<<592, 256>>>(src, dst, W2e, b2e);
    k_mlp<128, true, true><<<296, 256, smem128>>>(
        (const float*)p_h, (const float*)p_agg, eps2, nnW2, nnb2, g2, bb2, m2, v2, (float*)p_h2);

    // GATv2 linear transforms
    k_mlp<128, false, false><<<296, 256, smem128>>>(
        (const float*)p_h2, nullptr, nullptr, Wl, bl, nullptr, nullptr, nullptr, nullptr, (float*)p_xl);
    k_mlp<128, false, false><<<296, 256, smem128>>>(
        (const float*)p_h2, nullptr, nullptr, Wr, br, nullptr, nullptr, nullptr, nullptr, (float*)p_xr);

    // GATv2 attention
    k_gat_node<<<(N_ + 7) / 8, 256>>>(Weg, att);
    k_gat_edge<<<592, 256>>>(src, dst, Weg, att);
    k_final<<<(N_ * 64 + 255) / 256, 256>>>(out, gbias);
}

// round 4
// speedup vs baseline: 1.3774x; 1.3774x over previous
#include <cuda_runtime.h>
#include <cstdint>

#define N_ 50000
#define E_ 800000

// ---------------- scratch (device globals; no allocation) ----------------
__device__ __align__(16) float d_x   [N_*36];
__device__ __align__(16) float d_ea  [E_*16];
__device__ __align__(16) float d_agg [N_*128];
__device__ __align__(16) float d_h   [N_*128];
__device__ __align__(16) float d_h2  [N_*128];
__device__ __align__(16) float d_xl  [N_*128];
__device__ __align__(16) float d_xr  [N_*128];
__device__ __align__(16) float d_den  [N_*2];
__device__ __align__(16) float d_out2[N_*128];
__device__ __align__(16) float d_easum[16];

// ---------------- helpers ----------------
__device__ __forceinline__ void redAdd4(float* addr, float a, float b, float c, float d) {
    asm volatile("red.global.add.v4.f32 [%0], {%1, %2, %3, %4};"
                 :: "l"(addr), "f"(a), "f"(b), "f"(c), "f"(d) : "memory");
}

__device__ __forceinline__ float lrelu(float x) {
    return x > 0.0f ? x : 0.2f * x;
}

#define FMA4(acc, s, wv) { acc.x += (s)*(wv).x; acc.y += (s)*(wv).y; acc.z += (s)*(wv).z; acc.w += (s)*(wv).w; }
#define FMA16v(acc, Wr) { \
    FMA4(acc, e0.x, Wr[0]);  FMA4(acc, e0.y, Wr[1]);  FMA4(acc, e0.z, Wr[2]);  FMA4(acc, e0.w, Wr[3]); \
    FMA4(acc, e1.x, Wr[4]);  FMA4(acc, e1.y, Wr[5]);  FMA4(acc, e1.z, Wr[6]);  FMA4(acc, e1.w, Wr[7]); \
    FMA4(acc, e2.x, Wr[8]);  FMA4(acc, e2.y, Wr[9]);  FMA4(acc, e2.z, Wr[10]); FMA4(acc, e2.w, Wr[11]); \
    FMA4(acc, e3.x, Wr[12]); FMA4(acc, e3.y, Wr[13]); FMA4(acc, e3.z, Wr[14]); FMA4(acc, e3.w, Wr[15]); }

// ---------------- feature assembly ----------------
__global__ void k_node_feat(const int* __restrict__ xcat, const float* __restrict__ xcont,
                            const float* __restrict__ emb) {
    int i = blockIdx.x * blockDim.x + threadIdx.x;
    if (i >= N_ * 36) return;
    int n = i / 36, j = i - n * 36;
    float v;
    if (j < 20) v = emb[xcat[n] * 20 + j];
    else        v = xcont[n * 16 + (j - 20)];
    d_x[i] = v;
}

__global__ void k_edge_feat(const int* __restrict__ ecat, const float* __restrict__ econt,
                            const float* __restrict__ emb) {
    int i = blockIdx.x * blockDim.x + threadIdx.x;
    if (i >= E_ * 16) return;
    int e = i >> 4, j = i & 15;
    float v;
    if (j < 4) v = emb[ecat[e] * 4 + j];
    else       v = econt[e * 12 + (j - 4)];
    d_ea[i] = v;
}

// sum of ea over edges (for self-loop edge attr mean)
__global__ void k_easum() {
    int tid = blockIdx.x * blockDim.x + threadIdx.x;
    int stride = gridDim.x * blockDim.x;
    float a[16];
#pragma unroll
    for (int j = 0; j < 16; j++) a[j] = 0.0f;
    for (int e = tid; e < E_; e += stride) {
        const float4* p = ((const float4*)d_ea) + (size_t)e * 4;
        float4 v0 = p[0], v1 = p[1], v2 = p[2], v3 = p[3];
        a[0]+=v0.x; a[1]+=v0.y; a[2]+=v0.z; a[3]+=v0.w;
        a[4]+=v1.x; a[5]+=v1.y; a[6]+=v1.z; a[7]+=v1.w;
        a[8]+=v2.x; a[9]+=v2.y; a[10]+=v2.z; a[11]+=v2.w;
        a[12]+=v3.x; a[13]+=v3.y; a[14]+=v3.z; a[15]+=v3.w;
    }
#pragma unroll
    for (int off = 16; off; off >>= 1)
#pragma unroll
        for (int j = 0; j < 16; j++) a[j] += __shfl_down_sync(0xffffffffu, a[j], off);
    if ((threadIdx.x & 31) == 0)
#pragma unroll
        for (int j = 0; j < 16; j++) atomicAdd(&d_easum[j], a[j]);
}

// ---------------- GINE1 fused: register weights, pipelined (F=36) ----------------
__global__ __launch_bounds__(256, 2) void k_gine1(const int* __restrict__ src, const int* __restrict__ dst,
                                                  const float* __restrict__ W, const float* __restrict__ b) {
    int lane = threadIdx.x & 31;
    int gw = (blockIdx.x * 256 + threadIdx.x) >> 5;
    int nw = (gridDim.x * 256) >> 5;
    // lane owns channel `lane`; lanes 0-3 also own channel 32+lane
    float W1[16], W2[16];
#pragma unroll
    for (int k = 0; k < 16; k++) { W1[k] = W[k * 36 + lane]; W2[k] = W[k * 36 + 32 + (lane & 3)]; }
    float b1 = b[lane], b2 = b[32 + (lane & 3)];

    int e = gw;
    int s = 0, d = 0;
    float4 e0, e1, e2, e3;
    if (e < E_) {
        s = src[e]; d = dst[e];
        const float4* p = ((const float4*)d_ea) + (size_t)e * 4;
        e0 = p[0]; e1 = p[1]; e2 = p[2]; e3 = p[3];
    }
    while (e < E_) {
        int en = e + nw;
        int s2 = 0, d2 = 0;
        float4 f0, f1, f2, f3;
        if (en < E_) {
            s2 = src[en]; d2 = dst[en];
            const float4* p = ((const float4*)d_ea) + (size_t)en * 4;
            f0 = p[0]; f1 = p[1]; f2 = p[2]; f3 = p[3];
        }
        // gather x early
        float x1 = d_x[(size_t)s * 36 + lane];
        float x2 = d_x[(size_t)s * 36 + 32 + (lane & 3)];
        float acc1 = b1, acc2 = b2;
        float ev[16] = {e0.x,e0.y,e0.z,e0.w, e1.x,e1.y,e1.z,e1.w,
                        e2.x,e2.y,e2.z,e2.w, e3.x,e3.y,e3.z,e3.w};
#pragma unroll
        for (int k = 0; k < 16; k++) { acc1 += ev[k] * W1[k]; acc2 += ev[k] * W2[k]; }
        float m1 = fmaxf(x1 + acc1, 0.0f);
        float m2 = fmaxf(x2 + acc2, 0.0f);
        // pack 36 values into 9 lanes x float4
        float a0 = __shfl_sync(0xffffffffu, m1, (lane << 2) & 31);
        float a1 = __shfl_sync(0xffffffffu, m1, ((lane << 2) + 1) & 31);
        float a2 = __shfl_sync(0xffffffffu, m1, ((lane << 2) + 2) & 31);
        float a3 = __shfl_sync(0xffffffffu, m1, ((lane << 2) + 3) & 31);
        float c0 = __shfl_sync(0xffffffffu, m2, 0);
        float c1 = __shfl_sync(0xffffffffu, m2, 1);
        float c2 = __shfl_sync(0xffffffffu, m2, 2);
        float c3 = __shfl_sync(0xffffffffu, m2, 3);
        float v0 = (lane < 8) ? a0 : c0;
        float v1 = (lane < 8) ? a1 : c1;
        float v2 = (lane < 8) ? a2 : c2;
        float v3 = (lane < 8) ? a3 : c3;
        if (lane < 9)
            redAdd4(&d_agg[(size_t)d * 36 + (lane << 2)], v0, v1, v2, v3);
        e = en; s = s2; d = d2; e0 = f0; e1 = f1; e2 = f2; e3 = f3;
    }
}

// ---------------- GINE2 fused: register weights, pipelined (F=128) ----------------
__global__ __launch_bounds__(256, 2) void k_gine2(const int* __restrict__ src, const int* __restrict__ dst,
                                                  const float* __restrict__ W, const float* __restrict__ b) {
    int lane = threadIdx.x & 31;
    int gw = (blockIdx.x * 256 + threadIdx.x) >> 5;
    int nw = (gridDim.x * 256) >> 5;
    float4 Wr[16];
#pragma unroll
    for (int k = 0; k < 16; k++) Wr[k] = ((const float4*)W)[k * 32 + lane];
    float4 bv = ((const float4*)b)[lane];

    int e = gw;
    int s = 0, d = 0;
    float4 e0, e1, e2, e3;
    if (e < E_) {
        s = src[e]; d = dst[e];
        const float4* p = ((const float4*)d_ea) + (size_t)e * 4;
        e0 = p[0]; e1 = p[1]; e2 = p[2]; e3 = p[3];
    }
    while (e < E_) {
        int en = e + nw;
        int s2 = 0, d2 = 0;
        float4 f0, f1, f2, f3;
        if (en < E_) {
            s2 = src[en]; d2 = dst[en];
            const float4* p = ((const float4*)d_ea) + (size_t)en * 4;
            f0 = p[0]; f1 = p[1]; f2 = p[2]; f3 = p[3];
        }
        float4 hv = ((const float4*)d_h)[(size_t)s * 32 + lane];   // gather early
        float4 acc = bv;
        FMA16v(acc, Wr);
        redAdd4(&d_agg[(size_t)d * 128 + lane * 4],
                fmaxf(hv.x + acc.x, 0.0f), fmaxf(hv.y + acc.y, 0.0f),
                fmaxf(hv.z + acc.z, 0.0f), fmaxf(hv.w + acc.w, 0.0f));
        e = en; s = s2; d = d2; e0 = f0; e1 = f1; e2 = f2; e3 = f3;
    }
}

// ---------------- node MLP, register-tiled: 4 rows per thread ----------------
template <int K, bool HASAGG, bool HASBN>
__global__ __launch_bounds__(256) void k_mlp(
    const float* __restrict__ xin, const float* __restrict__ agg,
    const float* __restrict__ epsp,
    const float* __restrict__ W, const float* __restrict__ bias,
    const float* __restrict__ bng, const float* __restrict__ bnb,
    const float* __restrict__ bnm, const float* __restrict__ bnv,
    float* __restrict__ out)
{
    extern __shared__ float sm[];
    float* Ws  = sm;             // K*128
    float* tin = sm + K * 128;   // 32*K
    int tid = threadIdx.x;
    int lane = tid & 31, w = tid >> 5;
    for (int i = tid; i < K * 32; i += 256) ((float4*)Ws)[i] = ((const float4*)W)[i];
    int c = lane * 4;
    float4 bv = *(const float4*)(bias + c);
    float4 scale = make_float4(1,1,1,1), shift = make_float4(0,0,0,0);
    if (HASBN) {
        float s0 = bng[c+0] * rsqrtf(bnv[c+0] + 1e-5f);
        float s1 = bng[c+1] * rsqrtf(bnv[c+1] + 1e-5f);
        float s2 = bng[c+2] * rsqrtf(bnv[c+2] + 1e-5f);
        float s3 = bng[c+3] * rsqrtf(bnv[c+3] + 1e-5f);
        scale = make_float4(s0, s1, s2, s3);
        shift = make_float4(bnb[c+0] - bnm[c+0]*s0, bnb[c+1] - bnm[c+1]*s1,
                            bnb[c+2] - bnm[c+2]*s2, bnb[c+3] - bnm[c+3]*s3);
    }
    float sx = HASAGG ? (1.0f + *epsp) : 1.0f;
    __syncthreads();

    for (int base = blockIdx.x * 32; base < N_; base += gridDim.x * 32) {
        for (int i = tid; i < 32 * K; i += 256) {
            int r = i / K, k = i - r * K;
            int n = base + r;
            if (n < N_) {
                float tv = xin[(size_t)n * K + k] * sx;
                if (HASAGG) tv += agg[(size_t)n * K + k];
                tin[i] = tv;
            }
        }
        __syncthreads();
        const float* t0 = tin + (w * 4) * K;
        float4 a0 = bv, a1 = bv, a2 = bv, a3 = bv;
#pragma unroll 8
        for (int k = 0; k < K; k++) {
            float4 wv = *(const float4*)(Ws + k * 128 + c);
            float k0 = t0[k], k1 = t0[K + k], k2 = t0[2 * K + k], k3 = t0[3 * K + k];
            FMA4(a0, k0, wv); FMA4(a1, k1, wv); FMA4(a2, k2, wv); FMA4(a3, k3, wv);
        }
        if (HASBN) {
            a0.x = fmaxf(a0.x,0.f)*scale.x+shift.x; a0.y = fmaxf(a0.y,0.f)*scale.y+shift.y;
            a0.z = fmaxf(a0.z,0.f)*scale.z+shift.z; a0.w = fmaxf(a0.w,0.f)*scale.w+shift.w;
            a1.x = fmaxf(a1.x,0.f)*scale.x+shift.x; a1.y = fmaxf(a1.y,0.f)*scale.y+shift.y;
            a1.z = fmaxf(a1.z,0.f)*scale.z+shift.z; a1.w = fmaxf(a1.w,0.f)*scale.w+shift.w;
            a2.x = fmaxf(a2.x,0.f)*scale.x+shift.x; a2.y = fmaxf(a2.y,0.f)*scale.y+shift.y;
            a2.z = fmaxf(a2.z,0.f)*scale.z+shift.z; a2.w = fmaxf(a2.w,0.f)*scale.w+shift.w;
            a3.x = fmaxf(a3.x,0.f)*scale.x+shift.x; a3.y = fmaxf(a3.y,0.f)*scale.y+shift.y;
            a3.z = fmaxf(a3.z,0.f)*scale.z+shift.z; a3.w = fmaxf(a3.w,0.f)*scale.w+shift.w;
        }
        int n0 = base + w * 4;
        if (n0 + 0 < N_) *(float4*)(out + (size_t)(n0+0) * 128 + c) = a0;
        if (n0 + 1 < N_) *(float4*)(out + (size_t)(n0+1) * 128 + c) = a1;
        if (n0 + 2 < N_) *(float4*)(out + (size_t)(n0+2) * 128 + c) = a2;
        if (n0 + 3 < N_) *(float4*)(out + (size_t)(n0+3) * 128 + c) = a3;
        __syncthreads();
    }
}

// ---------------- GATv2 node pass: self-loop initializes out2/den ----------------
__global__ void k_gat_node(const float* __restrict__ Wg, const float* __restrict__ attv) {
    __shared__ float eeLs[128];
    __shared__ float4 atts[32];
    int t = threadIdx.x;
    if (t < 128) {
        float s = 0.0f;
#pragma unroll
        for (int k = 0; k < 16; k++) s += d_easum[k] * Wg[k * 128 + t];
        eeLs[t] = s * (1.0f / (float)E_);
    }
    if (t < 32) atts[t] = ((const float4*)attv)[t];
    __syncthreads();
    int n = (blockIdx.x * blockDim.x + t) >> 5;
    int lane = t & 31;
    if (n >= N_) return;
    float4 ev  = ((const float4*)eeLs)[lane];
    float4 xlv = ((const float4*)d_xl)[(size_t)n * 32 + lane];
    float4 xrv = ((const float4*)d_xr)[(size_t)n * 32 + lane];
    float4 av = atts[lane];
    float p = lrelu(xlv.x + xrv.x + ev.x) * av.x
            + lrelu(xlv.y + xrv.y + ev.y) * av.y
            + lrelu(xlv.z + xrv.z + ev.z) * av.z
            + lrelu(xlv.w + xrv.w + ev.w) * av.w;
    p += __shfl_xor_sync(0xffffffffu, p, 1);
    p += __shfl_xor_sync(0xffffffffu, p, 2);
    p += __shfl_xor_sync(0xffffffffu, p, 4);
    p += __shfl_xor_sync(0xffffffffu, p, 8);
    float ex = __expf(p);
    ((float4*)d_out2)[(size_t)n * 32 + lane] =
        make_float4(ex * xlv.x, ex * xlv.y, ex * xlv.z, ex * xlv.w);
    if (lane == 0)  d_den[(size_t)n * 2 + 0] = ex;
    if (lane == 16) d_den[(size_t)n * 2 + 1] = ex;
}

// ---------------- GATv2 edge pass: register weights, pipelined, single pass ----------------
__global__ __launch_bounds__(256, 2) void k_gat_edge(const int* __restrict__ src, const int* __restrict__ dst,
                                                     const float* __restrict__ Wg, const float* __restrict__ attv) {
    int lane = threadIdx.x & 31;
    int gw = (blockIdx.x * 256 + threadIdx.x) >> 5;
    int nw = (gridDim.x * 256) >> 5;
    float4 Wr[16];
#pragma unroll
    for (int k = 0; k < 16; k++) Wr[k] = ((const float4*)Wg)[k * 32 + lane];
    float4 av = ((const float4*)attv)[lane];

    int e = gw;
    int s = 0, d = 0;
    float4 e0, e1, e2, e3;
    if (e < E_) {
        s = src[e]; d = dst[e];
        const float4* p = ((const float4*)d_ea) + (size_t)e * 4;
        e0 = p[0]; e1 = p[1]; e2 = p[2]; e3 = p[3];
    }
    while (e < E_) {
        int en = e + nw;
        int s2 = 0, d2 = 0;
        float4 f0, f1, f2, f3;
        if (en < E_) {
            s2 = src[en]; d2 = dst[en];
            const float4* p = ((const float4*)d_ea) + (size_t)en * 4;
            f0 = p[0]; f1 = p[1]; f2 = p[2]; f3 = p[3];
        }
        float4 xlv = ((const float4*)d_xl)[(size_t)s * 32 + lane];  // gathers early
        float4 xrv = ((const float4*)d_xr)[(size_t)d * 32 + lane];
        float4 acc = make_float4(0, 0, 0, 0);
        FMA16v(acc, Wr);
        float p = lrelu(xlv.x + xrv.x + acc.x) * av.x
                + lrelu(xlv.y + xrv.y + acc.y) * av.y
                + lrelu(xlv.z + xrv.z + acc.z) * av.z
                + lrelu(xlv.w + xrv.w + acc.w) * av.w;
        p += __shfl_xor_sync(0xffffffffu, p, 1);
        p += __shfl_xor_sync(0xffffffffu, p, 2);
        p += __shfl_xor_sync(0xffffffffu, p, 4);
        p += __shfl_xor_sync(0xffffffffu, p, 8);
        float ex = __expf(p);
        redAdd4(&d_out2[(size_t)d * 128 + lane * 4],
                ex * xlv.x, ex * xlv.y, ex * xlv.z, ex * xlv.w);
        if (lane == 0)  atomicAdd(&d_den[(size_t)d * 2 + 0], ex);
        if (lane == 16) atomicAdd(&d_den[(size_t)d * 2 + 1], ex);
        e = en; s = s2; d = d2; e0 = f0; e1 = f1; e2 = f2; e3 = f3;
    }
}

__global__ void k_final(float* __restrict__ out, const float* __restrict__ bias) {
    int i = blockIdx.x * blockDim.x + threadIdx.x;
    if (i >= N_ * 64) return;
    int n = i >> 6, cc = i & 63;
    float2 dn = ((const float2*)d_den)[n];
    const float* o2 = d_out2 + (size_t)n * 128;
    out[i] = 0.5f * (o2[cc] / dn.x + o2[64 + cc] / dn.y) + bias[cc];
}

// ---------------- launch ----------------
extern "C" void kernel_launch(void* const* d_in, const int* in_sizes, int n_in,
                              void* d_out, int out_size) {
    const int*   x_cat    = (const int*)  d_in[0];
    const float* x_cont   = (const float*)d_in[1];
    const int*   e_cat    = (const int*)  d_in[2];
    const float* e_cont   = (const float*)d_in[3];
    const int*   eidx     = (const int*)  d_in[4];
    const int*   src = eidx;
    const int*   dst = eidx + E_;
    const float* node_emb = (const float*)d_in[5];
    const float* edge_emb = (const float*)d_in[6];
    const float* eps1     = (const float*)d_in[7];
    const float* W1e      = (const float*)d_in[8];
    const float* b1e      = (const float*)d_in[9];
    const float* nnW1     = (const float*)d_in[10];
    const float* nnb1     = (const float*)d_in[11];
    const float* g1 = (const float*)d_in[12], *bb1 = (const float*)d_in[13];
    const float* m1 = (const float*)d_in[14], *v1  = (const float*)d_in[15];
    const float* eps2     = (const float*)d_in[16];
    const float* W2e      = (const float*)d_in[17];
    const float* b2e      = (const float*)d_in[18];
    const float* nnW2     = (const float*)d_in[19];
    const float* nnb2     = (const float*)d_in[20];
    const float* g2 = (const float*)d_in[21], *bb2 = (const float*)d_in[22];
    const float* m2 = (const float*)d_in[23], *v2  = (const float*)d_in[24];
    const float* Wl  = (const float*)d_in[25], *bl = (const float*)d_in[26];
    const float* Wr  = (const float*)d_in[27], *br = (const float*)d_in[28];
    const float* Weg = (const float*)d_in[29];
    const float* att = (const float*)d_in[30];
    const float* gbias = (const float*)d_in[31];
    float* out = (float*)d_out;

    void *p_x, *p_agg, *p_h, *p_h2, *p_xl, *p_xr, *p_easum;
    cudaGetSymbolAddress(&p_x,    d_x);
    cudaGetSymbolAddress(&p_agg,  d_agg);
    cudaGetSymbolAddress(&p_h,    d_h);
    cudaGetSymbolAddress(&p_h2,   d_h2);
    cudaGetSymbolAddress(&p_xl,   d_xl);
    cudaGetSymbolAddress(&p_xr,   d_xr);
    cudaGetSymbolAddress(&p_easum,d_easum);

    const int smem36  = (36 * 128 + 32 * 36) * 4;
    const int smem128 = (128 * 128 + 32 * 128) * 4;
    cudaFuncSetAttribute(k_mlp<128, true,  true >, cudaFuncAttributeMaxDynamicSharedMemorySize, smem128);
    cudaFuncSetAttribute(k_mlp<128, false, false>, cudaFuncAttributeMaxDynamicSharedMemorySize, smem128);

    // init
    cudaMemsetAsync(p_easum, 0, 16 * 4);
    cudaMemsetAsync(p_agg,   0, (size_t)N_ * 36 * 4);

    // features
    k_node_feat<<<(N_ * 36 + 255) / 256, 256>>>(x_cat, x_cont, node_emb);
    k_edge_feat<<<(E_ * 16 + 255) / 256, 256>>>(e_cat, e_cont, edge_emb);
    k_easum<<<512, 256>>>();

    // GINE layer 1 (fused, register weights, persistent)
    k_gine1<<<296, 256>>>(src, dst, W1e, b1e);
    k_mlp<36, true, true><<<296, 256, smem36>>>(
        (const float*)p_x, (const float*)p_agg, eps1, nnW1, nnb1, g1, bb1, m1, v1, (float*)p_h);

    // GINE layer 2 (fused, register weights, persistent)
    cudaMemsetAsync(p_agg, 0, (size_t)N_ * 128 * 4);
    k_gine2<<<296, 256>>>(src, dst, W2e, b2e);
    k_mlp<128, true, true><<<296, 256, smem128>>>(
        (const float*)p_h, (const float*)p_agg, eps2, nnW2, nnb2, g2, bb2, m2, v2, (float*)p_h2);

    // GATv2 linear transforms
    k_mlp<128, false, false><<<296, 256, smem128>>>(
        (const float*)p_h2, nullptr, nullptr, Wl, bl, nullptr, nullptr, nullptr, nullptr, (float*)p_xl);
    k_mlp<128, false, false><<<296, 256, smem128>>>(
        (const float*)p_h2, nullptr, nullptr, Wr, br, nullptr, nullptr, nullptr, nullptr, (float*)p_xr);

    // GATv2 attention
    k_gat_node<<<(N_ + 7) / 8, 256>>>(Weg, att);
    k_gat_edge<<<296, 256>>>(src, dst, Weg, att);
    k_final<<<(N_ * 64 + 255) / 256, 256>>>(out, gbias);
}